// round 16
// baseline (speedup 1.0000x reference)
#include <cuda_runtime.h>
#include <cuda_fp16.h>
#include <cstdint>

// ---------------------------------------------------------------------------
// CrossAttention, single-product fp16 GEMMs (legacy mma.sync, sm_103).
// GN affine+transpose fused into Qproj A-path; multi-stream context overlap;
// sim+softmax+PV fused (P in smem).
// ---------------------------------------------------------------------------

constexpr int NB   = 16;
constexpr int ND   = 512;
constexpr int NHW  = 4096;
constexpr int NS   = 256;
constexpr int NCTX = 768;
constexpr int NCPG = 16;
#define EPSV 1e-5f

typedef __half h16;

__device__ __forceinline__ uint32_t h2_as_u32(__half2 v)
{
    return *reinterpret_cast<uint32_t*>(&v);
}

// ---- scratch (device globals; allocation-free) ----
__device__ float g_sc[NB * ND];
__device__ float g_sh[NB * ND];
__device__ __align__(256) h16 g_qh [(size_t)NB * NHW * ND];   // A of sim
__device__ __align__(256) h16 g_aoh[(size_t)NB * NHW * ND];   // B of Oproj
__device__ __align__(256) h16 g_cnh[NB * NS * NCTX];          // A of Kproj / B of Vproj
__device__ __align__(256) h16 g_kh [NB * NS * ND];            // B of sim
__device__ __align__(256) h16 g_vh [NB * ND * NS];            // B of PV ([c][s])
__device__ __align__(256) h16 g_wqh [ND * ND];
__device__ __align__(256) h16 g_wkvh[1024 * NCTX];
__device__ __align__(256) h16 g_woh [ND * ND];

// ---------------------------------------------------------------------------
// GroupNorm stats -> per-(b,c) scale/shift
// ---------------------------------------------------------------------------
__global__ void gn_stats_k(const float* __restrict__ x,
                           const float* __restrict__ gw,
                           const float* __restrict__ gb)
{
    int bg = blockIdx.x;
    int b = bg >> 5, g = bg & 31;
    const float4* p4 = (const float4*)(x + (size_t)bg * (NCPG * NHW));
    float s = 0.f, s2 = 0.f;
    const int n4 = NCPG * NHW / 4;
    for (int i = threadIdx.x; i < n4; i += 256) {
        float4 v = p4[i];
        s  += v.x + v.y + v.z + v.w;
        s2 += v.x*v.x + v.y*v.y + v.z*v.z + v.w*v.w;
    }
    #pragma unroll
    for (int o = 16; o > 0; o >>= 1) {
        s  += __shfl_down_sync(0xffffffffu, s,  o);
        s2 += __shfl_down_sync(0xffffffffu, s2, o);
    }
    __shared__ float shs[8], shs2[8];
    int lane = threadIdx.x & 31, w = threadIdx.x >> 5;
    if (lane == 0) { shs[w] = s; shs2[w] = s2; }
    __syncthreads();
    __shared__ float mm, rr;
    if (threadIdx.x == 0) {
        float ts = 0.f, ts2 = 0.f;
        #pragma unroll
        for (int i = 0; i < 8; i++) { ts += shs[i]; ts2 += shs2[i]; }
        float inv_n = 1.f / (float)(NCPG * NHW);
        float mean = ts * inv_n;
        float var  = ts2 * inv_n - mean * mean;
        mm = mean; rr = rsqrtf(var + EPSV);
    }
    __syncthreads();
    if (threadIdx.x < NCPG) {
        int ch = g * NCPG + threadIdx.x;
        float wv = gw[ch], bv = gb[ch];
        g_sc[b * ND + ch] = rr * wv;
        g_sh[b * ND + ch] = bv - mm * rr * wv;
    }
}

// ---------------------------------------------------------------------------
// LayerNorm on context rows -> cn fp16
// ---------------------------------------------------------------------------
__global__ void ln_k(const float* __restrict__ ctx,
                     const float* __restrict__ lw,
                     const float* __restrict__ lb)
{
    int row = blockIdx.x;
    const float* p = ctx + (size_t)row * NCTX;
    float v[3];
    float s = 0.f, s2 = 0.f;
    #pragma unroll
    for (int r = 0; r < 3; r++) {
        v[r] = p[threadIdx.x + r * 256];
        s += v[r]; s2 += v[r] * v[r];
    }
    #pragma unroll
    for (int o = 16; o > 0; o >>= 1) {
        s  += __shfl_down_sync(0xffffffffu, s,  o);
        s2 += __shfl_down_sync(0xffffffffu, s2, o);
    }
    __shared__ float shs[8], shs2[8];
    int lane = threadIdx.x & 31, w = threadIdx.x >> 5;
    if (lane == 0) { shs[w] = s; shs2[w] = s2; }
    __syncthreads();
    __shared__ float mm, rr;
    if (threadIdx.x == 0) {
        float ts = 0.f, ts2 = 0.f;
        #pragma unroll
        for (int i = 0; i < 8; i++) { ts += shs[i]; ts2 += shs2[i]; }
        float inv_n = 1.f / (float)NCTX;
        float mean = ts * inv_n;
        float var  = ts2 * inv_n - mean * mean;
        mm = mean; rr = rsqrtf(var + EPSV);
    }
    __syncthreads();
    #pragma unroll
    for (int r = 0; r < 3; r++) {
        int i = threadIdx.x + r * 256;
        float val = (v[r] - mm) * rr * lw[i] + lb[i];
        g_cnh[(size_t)row * NCTX + i] = __float2half_rn(val);
    }
}

// ---------------------------------------------------------------------------
// weights fp32 -> fp16
// ---------------------------------------------------------------------------
__global__ void convw1_k(const float* __restrict__ w, h16* __restrict__ hi, int n)
{
    int i = blockIdx.x * 1024 + threadIdx.x * 4;
    if (i < n) {
        float4 v = *(const float4*)(w + i);
        *(__half2*)(hi + i)     = __floats2half2_rn(v.x, v.y);
        *(__half2*)(hi + i + 2) = __floats2half2_rn(v.z, v.w);
    }
}

// ---------------------------------------------------------------------------
// PTX helpers
// ---------------------------------------------------------------------------
__device__ __forceinline__ uint32_t smem_u32(const void* p) {
    uint32_t a;
    asm("{.reg .u64 t; cvta.to.shared.u64 t, %1; cvt.u32.u64 %0, t;}" : "=r"(a) : "l"(p));
    return a;
}
__device__ __forceinline__ void mma16816(float* d, const uint32_t* a, const uint32_t* b)
{
    asm volatile(
        "mma.sync.aligned.m16n8k16.row.col.f32.f16.f16.f32 "
        "{%0,%1,%2,%3},{%4,%5,%6,%7},{%8,%9},{%0,%1,%2,%3};"
        : "+f"(d[0]), "+f"(d[1]), "+f"(d[2]), "+f"(d[3])
        : "r"(a[0]), "r"(a[1]), "r"(a[2]), "r"(a[3]), "r"(b[0]), "r"(b[1]));
}
__device__ __forceinline__ void ldsm4(uint32_t& r0, uint32_t& r1, uint32_t& r2,
                                      uint32_t& r3, uint32_t addr)
{
    asm volatile("ldmatrix.sync.aligned.m8n8.x4.shared.b16 {%0,%1,%2,%3},[%4];"
        : "=r"(r0), "=r"(r1), "=r"(r2), "=r"(r3) : "r"(addr));
}
__device__ __forceinline__ void cpa16(uint32_t saddr, const void* gaddr)
{
    asm volatile("cp.async.cg.shared.global [%0],[%1],16;" :: "r"(saddr), "l"(gaddr));
}
#define CP_COMMIT() asm volatile("cp.async.commit_group;" ::: "memory")

// ---------------------------------------------------------------------------
// fp16 GEMM: C[M,N] = A(MxK)*B(KxN); A [m][k], B [n][k].
// Block 128x128, BK=16, 256 threads (8 warps, warp 64x32), 3-stage cp.async.
// EPI 1: fp16 C = acc (+bias[n]); EPI 2: fp16 C = acc + bias[m];
// EPI 3: fp32 C = acc + bias[m] + resid.
// ---------------------------------------------------------------------------
constexpr int PLA  = 128 * 12 * 4;
constexpr int GST  = 2 * PLA;
constexpr int GSM  = 3 * GST;

template<int EPI>
__global__ __launch_bounds__(256, 2)
void gemm_fp16(const h16* __restrict__ Ah, const h16* __restrict__ Bh,
               void* __restrict__ C0,
               const float* __restrict__ bias, const float* __restrict__ resid,
               int K, int lda, int ldb, int ldc,
               long sA, long sB, long sC)
{
    extern __shared__ __align__(16) char dsm[];
    const uint32_t sbase = smem_u32(dsm);
    const int tid = threadIdx.x, lane = tid & 31, wid = tid >> 5;
    const int bz = blockIdx.z;
    const int m0 = blockIdx.x * 128;
    const int n0 = blockIdx.y * 128;

    const h16* Ap = Ah + (size_t)bz * sA;
    const h16* Bp = Bh + (size_t)bz * sB;
    const int nIter = K >> 4;

    const int lrow = tid >> 1, lch = tid & 1;
    const uint32_t so = (uint32_t)((lrow * 12 + lch * 4) * 4);
    const size_t gAo = (size_t)(m0 + lrow) * lda + lch * 8;
    const size_t gBo = (size_t)(n0 + lrow) * ldb + lch * 8;

    auto issue = [&](int s) {
        int k0 = s << 4;
        uint32_t st = sbase + (s % 3) * GST;
        cpa16(st + so,       Ap + gAo + k0);
        cpa16(st + PLA + so, Bp + gBo + k0);
        CP_COMMIT();
    };

    const int mw = (wid & 1) * 64, nw = (wid >> 1) * 32;
    const int lr = lane & 7;
    const uint32_t aoff = (uint32_t)(((mw + lr + 8 * ((lane >> 3) & 1)) * 12
                                      + (lane >> 4) * 4) * 4);
    const uint32_t boff = (uint32_t)(((nw + 8 * (lane >> 4) + lr) * 12
                                      + ((lane >> 3) & 1) * 4) * 4);
    const int g = lane >> 2, tg = lane & 3;

    float acc[4][4][4];
    #pragma unroll
    for (int i = 0; i < 4; i++)
        #pragma unroll
        for (int j = 0; j < 4; j++)
            #pragma unroll
            for (int q = 0; q < 4; q++) acc[i][j][q] = 0.f;

    issue(0); issue(1);

    for (int it = 0; it < nIter; it++) {
        if (it + 1 < nIter) asm volatile("cp.async.wait_group 1;" ::: "memory");
        else                asm volatile("cp.async.wait_group 0;" ::: "memory");
        __syncthreads();
        if (it + 2 < nIter) issue(it + 2);

        uint32_t st = sbase + (it % 3) * GST;
        uint32_t af[4][4], bh[4][2];
        ldsm4(bh[0][0], bh[0][1], bh[1][0], bh[1][1], st + PLA + boff);
        ldsm4(bh[2][0], bh[2][1], bh[3][0], bh[3][1], st + PLA + boff + 768);
        #pragma unroll
        for (int i = 0; i < 4; i++)
            ldsm4(af[i][0], af[i][1], af[i][2], af[i][3], st + aoff + i * 768);
        #pragma unroll
        for (int i = 0; i < 4; i++)
            #pragma unroll
            for (int j = 0; j < 4; j++)
                mma16816(acc[i][j], af[i], bh[j]);
    }

    if constexpr (EPI == 1 || EPI == 2) {
        h16* Ch = (h16*)C0 + (size_t)bz * sC;
        #pragma unroll
        for (int i = 0; i < 4; i++) {
            int r = m0 + mw + 16 * i + g;
            #pragma unroll
            for (int j = 0; j < 4; j++) {
                int c = n0 + nw + 8 * j + 2 * tg;
                float b0, b1, b2, b3;
                if constexpr (EPI == 1) {
                    b0 = bias ? bias[c] : 0.f; b1 = bias ? bias[c + 1] : 0.f;
                    b2 = b0; b3 = b1;
                } else {
                    b0 = b1 = bias[r]; b2 = b3 = bias[r + 8];
                }
                *(__half2*)(Ch + (size_t)r * ldc + c) =
                    __floats2half2_rn(acc[i][j][0] + b0, acc[i][j][1] + b1);
                *(__half2*)(Ch + (size_t)(r + 8) * ldc + c) =
                    __floats2half2_rn(acc[i][j][2] + b2, acc[i][j][3] + b3);
            }
        }
    } else {
        float* Co = (float*)C0 + (size_t)bz * sC;
        const float* R = resid + (size_t)bz * sC;
        #pragma unroll
        for (int i = 0; i < 4; i++) {
            int r = m0 + mw + 16 * i + g;
            float bv0 = bias[r], bv1 = bias[r + 8];
            #pragma unroll
            for (int j = 0; j < 4; j++) {
                int c = n0 + nw + 8 * j + 2 * tg;
                float2 rv0 = *(const float2*)(R + (size_t)r * ldc + c);
                float2 rv1 = *(const float2*)(R + (size_t)(r + 8) * ldc + c);
                *(float2*)(Co + (size_t)r * ldc + c) =
                    make_float2(acc[i][j][0] + bv0 + rv0.x, acc[i][j][1] + bv0 + rv0.y);
                *(float2*)(Co + (size_t)(r + 8) * ldc + c) =
                    make_float2(acc[i][j][2] + bv1 + rv1.x, acc[i][j][3] + bv1 + rv1.y);
            }
        }
    }
}

// ---------------------------------------------------------------------------
// Qproj with fused GroupNorm affine + transpose:
// q[p][c] = (x[:,p] * sc + sh) @ wq^T + bq, x native [c][p].
// A staged via reg->STS (double buffer), B (wq) 3-stage cp.async.
// ---------------------------------------------------------------------------
constexpr int QAPL = PLA;                 // 6144 per A buf
constexpr int QBO  = 2 * QAPL;            // B planes start
constexpr int QSM  = QBO + 3 * PLA;       // 12288 + 18432 = 30720

__global__ __launch_bounds__(256, 2)
void gemm_qproj(const float* __restrict__ x, const h16* __restrict__ wq,
                h16* __restrict__ qout, const float* __restrict__ bq)
{
    extern __shared__ __align__(16) char dsm[];
    const uint32_t sbase = smem_u32(dsm);
    const int tid = threadIdx.x, lane = tid & 31, wid = tid >> 5;
    const int bz = blockIdx.z;
    const int m0 = blockIdx.x * 128;
    const int n0 = blockIdx.y * 128;

    const float* xb = x + (size_t)bz * ND * NHW;
    const float* scb = g_sc + bz * ND;
    const float* shb = g_sh + bz * ND;

    const int nIter = ND >> 4;   // 32

    // --- A loader: thread handles p = tid&127, c-block cb = (tid>>7)*8 ---
    const int apx = tid & 127;
    const int acb = (tid >> 7) * 8;
    float rA[8];

    auto ldA = [&](int it) {
        int c0 = (it << 4) + acb;
        const float* xp = xb + (size_t)c0 * NHW + m0 + apx;
        #pragma unroll
        for (int j = 0; j < 8; j++) rA[j] = xp[(size_t)j * NHW];
    };
    auto stA = [&](int it) {
        int c0 = (it << 4) + acb;
        float4 s0 = *(const float4*)(scb + c0);
        float4 s1 = *(const float4*)(scb + c0 + 4);
        float4 t0 = *(const float4*)(shb + c0);
        float4 t1 = *(const float4*)(shb + c0 + 4);
        uint4 pk;
        pk.x = h2_as_u32(__floats2half2_rn(rA[0]*s0.x + t0.x, rA[1]*s0.y + t0.y));
        pk.y = h2_as_u32(__floats2half2_rn(rA[2]*s0.z + t0.z, rA[3]*s0.w + t0.w));
        pk.z = h2_as_u32(__floats2half2_rn(rA[4]*s1.x + t1.x, rA[5]*s1.y + t1.y));
        pk.w = h2_as_u32(__floats2half2_rn(rA[6]*s1.z + t1.z, rA[7]*s1.w + t1.w));
        *(uint4*)(dsm + (it & 1) * QAPL + (apx * 12 + (acb >> 3) * 4) * 4) = pk;
    };

    // --- B loader (cp.async, same as gemm_fp16) ---
    const int lrow = tid >> 1, lch = tid & 1;
    const uint32_t so = (uint32_t)((lrow * 12 + lch * 4) * 4);
    const size_t gBo = (size_t)(n0 + lrow) * ND + lch * 8;
    auto issueB = [&](int s) {
        int k0 = s << 4;
        cpa16(sbase + QBO + (s % 3) * PLA + so, wq + gBo + k0);
        CP_COMMIT();
    };

    const int mw = (wid & 1) * 64, nw = (wid >> 1) * 32;
    const int lr = lane & 7;
    const uint32_t aoff = (uint32_t)(((mw + lr + 8 * ((lane >> 3) & 1)) * 12
                                      + (lane >> 4) * 4) * 4);
    const uint32_t boff = (uint32_t)(((nw + 8 * (lane >> 4) + lr) * 12
                                      + ((lane >> 3) & 1) * 4) * 4);
    const int g = lane >> 2, tg = lane & 3;

    float acc[4][4][4];
    #pragma unroll
    for (int i = 0; i < 4; i++)
        #pragma unroll
        for (int j = 0; j < 4; j++)
            #pragma unroll
            for (int q = 0; q < 4; q++) acc[i][j][q] = 0.f;

    // prolog: A(0) staged, A(1) in regs, B(0..1) in flight
    ldA(0); stA(0);
    ldA(1);
    issueB(0); issueB(1);

    for (int it = 0; it < nIter; it++) {
        if (it + 1 < nIter) asm volatile("cp.async.wait_group 1;" ::: "memory");
        else                asm volatile("cp.async.wait_group 0;" ::: "memory");
        __syncthreads();   // A buf(it) + B stage(it) visible; prev compute done
        if (it + 2 < nIter) issueB(it + 2);
        if (it + 1 < nIter) stA(it + 1);   // buf (it+1)&1 — free (compute(it-1) synced)
        if (it + 2 < nIter) ldA(it + 2);

        uint32_t aP = sbase + (it & 1) * QAPL;
        uint32_t bP = sbase + QBO + (it % 3) * PLA;
        uint32_t af[4][4], bh[4][2];
        ldsm4(bh[0][0], bh[0][1], bh[1][0], bh[1][1], bP + boff);
        ldsm4(bh[2][0], bh[2][1], bh[3][0], bh[3][1], bP + boff + 768);
        #pragma unroll
        for (int i = 0; i < 4; i++)
            ldsm4(af[i][0], af[i][1], af[i][2], af[i][3], aP + aoff + i * 768);
        #pragma unroll
        for (int i = 0; i < 4; i++)
            #pragma unroll
            for (int j = 0; j < 4; j++)
                mma16816(acc[i][j], af[i], bh[j]);
    }

    h16* Ch = qout + (size_t)bz * NHW * ND;
    #pragma unroll
    for (int i = 0; i < 4; i++) {
        int r = m0 + mw + 16 * i + g;
        #pragma unroll
        for (int j = 0; j < 4; j++) {
            int c = n0 + nw + 8 * j + 2 * tg;
            float b0 = bq[c], b1 = bq[c + 1];
            *(__half2*)(Ch + (size_t)r * ND + c) =
                __floats2half2_rn(acc[i][j][0] + b0, acc[i][j][1] + b1);
            *(__half2*)(Ch + (size_t)(r + 8) * ND + c) =
                __floats2half2_rn(acc[i][j][2] + b0, acc[i][j][3] + b1);
        }
    }
}

// ---------------------------------------------------------------------------
// Fused sim -> softmax -> PV.  Tile: 128 queries x S=256 x full out D=512.
// 512 threads (16 warps: 2 m x 8 n). P kept in smem (swizzled 512B rows).
// ---------------------------------------------------------------------------
constexpr int ASPA = 128 * 12 * 4;        // 6144  (q plane)
constexpr int ASPB = 256 * 12 * 4;        // 12288 (k/v plane)
constexpr int ASST = ASPA + ASPB;         // 18432 per stage
constexpr int APOFF = 3 * ASST;           // 55296 (P tile, 64KB)
constexpr int ARM  = APOFF + 65536;       // 120832
constexpr int ARS  = ARM + 4608;          // 125440
constexpr int ASM  = ARS + 4608;          // 130048

__global__ __launch_bounds__(512)
void attn_k(const h16* __restrict__ qh, const h16* __restrict__ kh,
            const h16* __restrict__ vh, float qscale)
{
    extern __shared__ __align__(16) char dsm[];
    const uint32_t sbase = smem_u32(dsm);
    float* redM = (float*)(dsm + ARM);
    float* redS = (float*)(dsm + ARS);
    const int tid = threadIdx.x, lane = tid & 31, wid = tid >> 5;
    const int b = blockIdx.y, p0 = blockIdx.x * 128;

    const h16* Qp = qh + (size_t)b * NHW * ND;
    const h16* Kp = kh + (size_t)b * NS * ND;
    const h16* Vp = vh + (size_t)b * ND * NS;

    const int lrow = tid >> 1, lch = tid & 1;
    const uint32_t so = (uint32_t)((lrow * 12 + lch * 4) * 4);

    const int mwp = wid & 1, nwp = wid >> 1;
    const int mw = mwp * 64, nw = nwp * 32;
    const int lr = lane & 7;
    const uint32_t aoff = (uint32_t)(((mw + lr + 8 * ((lane >> 3) & 1)) * 12
                                      + (lane >> 4) * 4) * 4);
    const uint32_t boff = (uint32_t)(((nw + 8 * (lane >> 4) + lr) * 12
                                      + ((lane >> 3) & 1) * 4) * 4);
    const int g = lane >> 2, tg = lane & 3;

    float acc[4][4][4];
    #pragma unroll
    for (int i = 0; i < 4; i++)
        #pragma unroll
        for (int j = 0; j < 4; j++)
            #pragma unroll
            for (int q = 0; q < 4; q++) acc[i][j][q] = 0.f;

    // ---------------- phase 1: sim = q @ k^T ----------------
    auto issueQK = [&](int s) {
        int k0 = s << 4;
        uint32_t st = sbase + (s % 3) * ASST;
        if (tid < 256)
            cpa16(st + so, Qp + (size_t)(p0 + lrow) * ND + k0 + lch * 8);
        cpa16(st + ASPA + so, Kp + (size_t)lrow * ND + k0 + lch * 8);
        CP_COMMIT();
    };
    issueQK(0); issueQK(1);
    const int nI1 = ND >> 4;   // 32
    for (int it = 0; it < nI1; it++) {
        if (it + 1 < nI1) asm volatile("cp.async.wait_group 1;" ::: "memory");
        else              asm volatile("cp.async.wait_group 0;" ::: "memory");
        __syncthreads();
        if (it + 2 < nI1) issueQK(it + 2);

        uint32_t st = sbase + (it % 3) * ASST;
        uint32_t af[4][4], bh[4][2];
        ldsm4(bh[0][0], bh[0][1], bh[1][0], bh[1][1], st + ASPA + boff);
        ldsm4(bh[2][0], bh[2][1], bh[3][0], bh[3][1], st + ASPA + boff + 768);
        #pragma unroll
        for (int i = 0; i < 4; i++)
            ldsm4(af[i][0], af[i][1], af[i][2], af[i][3], st + aoff + i * 768);
        #pragma unroll
        for (int i = 0; i < 4; i++)
            #pragma unroll
            for (int j = 0; j < 4; j++)
                mma16816(acc[i][j], af[i], bh[j]);
    }

    // ---------------- softmax ----------------
    #pragma unroll
    for (int i = 0; i < 4; i++)
        #pragma unroll
        for (int j = 0; j < 4; j++)
            #pragma unroll
            for (int q = 0; q < 4; q++) acc[i][j][q] *= qscale;

    float rmx[4][2];
    #pragma unroll
    for (int i = 0; i < 4; i++)
        #pragma unroll
        for (int h = 0; h < 2; h++) {
            float m = -1e30f;
            #pragma unroll
            for (int j = 0; j < 4; j++)
                m = fmaxf(m, fmaxf(acc[i][j][2 * h], acc[i][j][2 * h + 1]));
            rmx[i][h] = m;
        }
    #pragma unroll
    for (int o = 1; o <= 2; o <<= 1)
        #pragma unroll
        for (int i = 0; i < 4; i++)
            #pragma unroll
            for (int h = 0; h < 2; h++)
                rmx[i][h] = fmaxf(rmx[i][h], __shfl_xor_sync(0xffffffffu, rmx[i][h], o));
    if (tg == 0) {
        #pragma unroll
        for (int i = 0; i < 4; i++)
            #pragma unroll
            for (int h = 0; h < 2; h++)
                redM[(mw + 16 * i + 8 * h + g) * 9 + nwp] = rmx[i][h];
    }
    __syncthreads();
    float rM[4][2];
    #pragma unroll
    for (int i = 0; i < 4; i++)
        #pragma unroll
        for (int h = 0; h < 2; h++) {
            int R = mw + 16 * i + 8 * h + g;
            float m = -1e30f;
            #pragma unroll
            for (int w = 0; w < 8; w++) m = fmaxf(m, redM[R * 9 + w]);
            rM[i][h] = m;
        }

    float rsm[4][2] = {{0.f,0.f},{0.f,0.f},{0.f,0.f},{0.f,0.f}};
    #pragma unroll
    for (int i = 0; i < 4; i++)
        #pragma unroll
        for (int j = 0; j < 4; j++)
            #pragma unroll
            for (int h = 0; h < 2; h++) {
                float e0 = __expf(acc[i][j][2*h]     - rM[i][h]);
                float e1 = __expf(acc[i][j][2*h + 1] - rM[i][h]);
                acc[i][j][2*h]     = e0;
                acc[i][j][2*h + 1] = e1;
                rsm[i][h] += e0 + e1;
            }
    #pragma unroll
    for (int o = 1; o <= 2; o <<= 1)
        #pragma unroll
        for (int i = 0; i < 4; i++)
            #pragma unroll
            for (int h = 0; h < 2; h++)
                rsm[i][h] += __shfl_xor_sync(0xffffffffu, rsm[i][h], o);
    if (tg == 0) {
        #pragma unroll
        for (int i = 0; i < 4; i++)
            #pragma unroll
            for (int h = 0; h < 2; h++)
                redS[(mw + 16 * i + 8 * h + g) * 9 + nwp] = rsm[i][h];
    }
    __syncthreads();

    // write P to smem (swizzled: unit u of row R at ((u ^ (R&7)) * 16))
    #pragma unroll
    for (int i = 0; i < 4; i++)
        #pragma unroll
        for (int h = 0; h < 2; h++) {
            int R = mw + 16 * i + 8 * h + g;
            float sum = 0.f;
            #pragma unroll
            for (int w = 0; w < 8; w++) sum += redS[R * 9 + w];
            float inv = 1.f / sum;
            #pragma unroll
            for (int j = 0; j < 4; j++) {
                int c = nw + 8 * j + 2 * tg;
                int u = c >> 3;
                char* pa = dsm + APOFF + R * 512 + ((u ^ (R & 7)) << 4) + (c & 7) * 2;
                *(__half2*)pa = __floats2half2_rn(acc[i][j][2*h] * inv,
                                                  acc[i][j][2*h + 1] * inv);
            }
        }
    __syncthreads();

    // ---------------- phase 2: PV = P @ v^T ----------------
    const uint32_t Pb = sbase + APOFF;
    const int arow = mw + (lane & 15);
    const uint32_t swz = (uint32_t)(arow & 7);
    const uint32_t uo = (uint32_t)(lane >> 4);
    uint32_t rowA[4];
    #pragma unroll
    for (int i = 0; i < 4; i++) rowA[i] = Pb + (arow + 16 * i) * 512;

    h16* Cp = g_aoh + ((size_t)b * NHW + p0) * ND;

    #pragma unroll 1
    for (int nc = 0; nc < 2; nc++) {
        #pragma unroll
        for (int i = 0; i < 4; i++)
            #pragma unroll
            for (int j = 0; j < 4; j++)
                #pragma unroll
                for (int q = 0; q < 4; q++) acc[i][j][q] = 0.f;

        auto issueV = [&](int s) {
            int s0 = s << 4;
            uint32_t st = sbase + (s % 3) * ASST;
            cpa16(st + so, Vp + (size_t)(nc * 256 + lrow) * NS + s0 + lch * 8);
            CP_COMMIT();
        };
        issueV(0); issueV(1);
        const int nI2 = NS >> 4;   // 16
        for (int it = 0; it < nI2; it++) {
            if (it + 1 < nI2) asm volatile("cp.async.wait_group 1;" ::: "memory");
            else              asm volatile("cp.async.wait_group 0;" ::: "memory");
            __syncthreads();
            if (it + 2 < nI2) issueV(it + 2);

            uint32_t st = sbase + (it % 3) * ASST;
            uint32_t af[4][4], bh[4][2];
            ldsm4(bh[0][0], bh[0][1], bh[1][0], bh[1][1], st + boff);
            ldsm4(bh[2][0], bh[2][1], bh[3][0], bh[3][1], st + boff + 768);
            #pragma unroll
            for (int i = 0; i < 4; i++) {
                uint32_t ua = ((2u * (uint32_t)it + uo) ^ swz) << 4;
                ldsm4(af[i][0], af[i][1], af[i][2], af[i][3], rowA[i] + ua);
            }
            #pragma unroll
            for (int i = 0; i < 4; i++)
                #pragma unroll
                for (int j = 0; j < 4; j++)
                    mma16816(acc[i][j], af[i], bh[j]);
        }

        // epilogue: write ao chunk
        #pragma unroll
        for (int i = 0; i < 4; i++) {
            int r = mw + 16 * i + g;
            #pragma unroll
            for (int j = 0; j < 4; j++) {
                int c = nc * 256 + nw + 8 * j + 2 * tg;
                *(__half2*)(Cp + (size_t)r * ND + c) =
                    __floats2half2_rn(acc[i][j][0], acc[i][j][1]);
                *(__half2*)(Cp + (size_t)(r + 8) * ND + c) =
                    __floats2half2_rn(acc[i][j][2], acc[i][j][3]);
            }
        }
        __syncthreads();
    }
}

// ---------------------------------------------------------------------------
extern "C" void kernel_launch(void* const* d_in, const int* in_sizes, int n_in,
                              void* d_out, int out_size)
{
    const float* x    = (const float*)d_in[0];
    const float* ctx  = (const float*)d_in[1];
    const float* gn_w = (const float*)d_in[2];
    const float* gn_b = (const float*)d_in[3];
    const float* ln_w = (const float*)d_in[4];
    const float* ln_b = (const float*)d_in[5];
    const float* wq   = (const float*)d_in[6];
    const float* bq   = (const float*)d_in[7];
    const float* wkv  = (const float*)d_in[8];
    const float* bkv  = (const float*)d_in[9];
    const float* wo   = (const float*)d_in[10];
    const float* bo   = (const float*)d_in[11];
    float* out = (float*)d_out;

    cudaFuncSetAttribute(gemm_fp16<1>, cudaFuncAttributeMaxDynamicSharedMemorySize, GSM);
    cudaFuncSetAttribute(gemm_fp16<2>, cudaFuncAttributeMaxDynamicSharedMemorySize, GSM);
    cudaFuncSetAttribute(gemm_fp16<3>, cudaFuncAttributeMaxDynamicSharedMemorySize, GSM);
    cudaFuncSetAttribute(gemm_qproj,   cudaFuncAttributeMaxDynamicSharedMemorySize, QSM);
    cudaFuncSetAttribute(attn_k, cudaFuncAttributeMaxDynamicSharedMemorySize, ASM);

    h16 *qh, *aoh, *cnh, *kh, *vh, *wqh, *wkvh, *woh;
    cudaGetSymbolAddress((void**)&qh,  g_qh);
    cudaGetSymbolAddress((void**)&aoh, g_aoh);
    cudaGetSymbolAddress((void**)&cnh, g_cnh);
    cudaGetSymbolAddress((void**)&kh,  g_kh);
    cudaGetSymbolAddress((void**)&vh,  g_vh);
    cudaGetSymbolAddress((void**)&wqh, g_wqh);
    cudaGetSymbolAddress((void**)&wkvh, g_wkvh);
    cudaGetSymbolAddress((void**)&woh, g_woh);

    const float qscale = 0.044194173824159216f; // 512^-0.5

    // one-time side-stream setup (first call is the uncaptured correctness run)
    static cudaStream_t s1 = nullptr;
    static cudaEvent_t eFork = nullptr, eWq = nullptr, eV = nullptr, eWo = nullptr;
    static bool sinit = false, ms = false;
    if (!sinit) {
        sinit = true;
        ms = (cudaStreamCreateWithFlags(&s1, cudaStreamNonBlocking) == cudaSuccess)
          && (cudaEventCreateWithFlags(&eFork, cudaEventDisableTiming) == cudaSuccess)
          && (cudaEventCreateWithFlags(&eWq,   cudaEventDisableTiming) == cudaSuccess)
          && (cudaEventCreateWithFlags(&eV,    cudaEventDisableTiming) == cudaSuccess)
          && (cudaEventCreateWithFlags(&eWo,   cudaEventDisableTiming) == cudaSuccess);
    }

    if (ms) {
        cudaEventRecord(eFork, 0);
        cudaStreamWaitEvent(s1, eFork, 0);

        // side stream: weight conversions + context path
        convw1_k<<<(ND * ND + 1023) / 1024, 256, 0, s1>>>(wq, wqh, ND * ND);
        cudaEventRecord(eWq, s1);
        convw1_k<<<(1024 * NCTX + 1023) / 1024, 256, 0, s1>>>(wkv, wkvh, 1024 * NCTX);
        ln_k<<<NB * NS, 256, 0, s1>>>(ctx, ln_w, ln_b);
        gemm_fp16<1><<<dim3(NS / 128, ND / 128, NB), 256, GSM, s1>>>(
            cnh, wkvh, kh, bkv, nullptr, NCTX, NCTX, NCTX, ND,
            (long)NS * NCTX, 0L, (long)NS * ND);
        gemm_fp16<2><<<dim3(ND / 128, NS / 128, NB), 256, GSM, s1>>>(
            wkvh + (size_t)512 * NCTX, cnh, vh, bkv + 512, nullptr,
            NCTX, NCTX, NCTX, NS, 0L, (long)NS * NCTX, (long)ND * NS);
        cudaEventRecord(eV, s1);
        convw1_k<<<(ND * ND + 1023) / 1024, 256, 0, s1>>>(wo, woh, ND * ND);
        cudaEventRecord(eWo, s1);

        // main stream: x path (GN affine fused into Qproj)
        gn_stats_k<<<NB * 32, 256>>>(x, gn_w, gn_b);
        cudaStreamWaitEvent(0, eWq, 0);
        gemm_qproj<<<dim3(NHW / 128, ND / 128, NB), 256, QSM>>>(x, wqh, qh, bq);
        cudaStreamWaitEvent(0, eV, 0);
        attn_k<<<dim3(NHW / 128, NB), 512, ASM>>>(qh, kh, vh, qscale);
        cudaStreamWaitEvent(0, eWo, 0);
        gemm_fp16<3><<<dim3(ND / 128, NHW / 128, NB), 256, GSM>>>(
            woh, aoh, out, bo, x, ND, ND, ND, NHW,
            0L, (long)NHW * ND, (long)ND * NHW);
    } else {
        // serial fallback
        convw1_k<<<(ND * ND + 1023) / 1024, 256>>>(wq, wqh, ND * ND);
        convw1_k<<<(1024 * NCTX + 1023) / 1024, 256>>>(wkv, wkvh, 1024 * NCTX);
        convw1_k<<<(ND * ND + 1023) / 1024, 256>>>(wo, woh, ND * ND);
        gn_stats_k<<<NB * 32, 256>>>(x, gn_w, gn_b);
        ln_k<<<NB * NS, 256>>>(ctx, ln_w, ln_b);
        gemm_fp16<1><<<dim3(NS / 128, ND / 128, NB), 256, GSM>>>(
            cnh, wkvh, kh, bkv, nullptr, NCTX, NCTX, NCTX, ND,
            (long)NS * NCTX, 0L, (long)NS * ND);
        gemm_fp16<2><<<dim3(ND / 128, NS / 128, NB), 256, GSM>>>(
            wkvh + (size_t)512 * NCTX, cnh, vh, bkv + 512, nullptr,
            NCTX, NCTX, NCTX, NS, 0L, (long)NS * NCTX, (long)ND * NS);
        gemm_qproj<<<dim3(NHW / 128, ND / 128, NB), 256, QSM>>>(x, wqh, qh, bq);
        attn_k<<<dim3(NHW / 128, NB), 512, ASM>>>(qh, kh, vh, qscale);
        gemm_fp16<3><<<dim3(ND / 128, NHW / 128, NB), 256, GSM>>>(
            woh, aoh, out, bo, x, ND, ND, ND, NHW,
            0L, (long)NHW * ND, (long)ND * NHW);
    }
}

// round 17
// speedup vs baseline: 1.1036x; 1.1036x over previous
#include <cuda_runtime.h>
#include <cuda_fp16.h>
#include <cstdint>

// ---------------------------------------------------------------------------
// CrossAttention, single-product fp16 GEMMs (legacy mma.sync, sm_103).
// R13 structure (xn_conv + generic GEMMs) + two half-batch x-path streams
// to overlap kernel tails; V prefetch hidden under softmax in attn_k.
// ---------------------------------------------------------------------------

constexpr int NB   = 16;
constexpr int ND   = 512;
constexpr int NHW  = 4096;
constexpr int NS   = 256;
constexpr int NCTX = 768;
constexpr int NCPG = 16;
#define EPSV 1e-5f

typedef __half h16;

// ---- scratch (device globals; allocation-free) ----
__device__ float g_sc[NB * ND];
__device__ float g_sh[NB * ND];
__device__ __align__(256) h16 g_xnh[(size_t)NB * NHW * ND];   // A of Qproj
__device__ __align__(256) h16 g_qh [(size_t)NB * NHW * ND];   // A of sim
__device__ __align__(256) h16 g_aoh[(size_t)NB * NHW * ND];   // B of Oproj
__device__ __align__(256) h16 g_cnh[NB * NS * NCTX];          // A of Kproj / B of Vproj
__device__ __align__(256) h16 g_kh [NB * NS * ND];            // B of sim
__device__ __align__(256) h16 g_vh [NB * ND * NS];            // B of PV ([c][s])
__device__ __align__(256) h16 g_wqh [ND * ND];
__device__ __align__(256) h16 g_wkvh[1024 * NCTX];
__device__ __align__(256) h16 g_woh [ND * ND];

// ---------------------------------------------------------------------------
// GroupNorm stats -> per-(b,c) scale/shift   (bg0 = batch-group base)
// ---------------------------------------------------------------------------
__global__ void gn_stats_k(const float* __restrict__ x,
                           const float* __restrict__ gw,
                           const float* __restrict__ gb, int bg0)
{
    int bg = blockIdx.x + bg0;
    int b = bg >> 5, g = bg & 31;
    const float4* p4 = (const float4*)(x + (size_t)bg * (NCPG * NHW));
    float s = 0.f, s2 = 0.f;
    const int n4 = NCPG * NHW / 4;
    for (int i = threadIdx.x; i < n4; i += 256) {
        float4 v = p4[i];
        s  += v.x + v.y + v.z + v.w;
        s2 += v.x*v.x + v.y*v.y + v.z*v.z + v.w*v.w;
    }
    #pragma unroll
    for (int o = 16; o > 0; o >>= 1) {
        s  += __shfl_down_sync(0xffffffffu, s,  o);
        s2 += __shfl_down_sync(0xffffffffu, s2, o);
    }
    __shared__ float shs[8], shs2[8];
    int lane = threadIdx.x & 31, w = threadIdx.x >> 5;
    if (lane == 0) { shs[w] = s; shs2[w] = s2; }
    __syncthreads();
    __shared__ float mm, rr;
    if (threadIdx.x == 0) {
        float ts = 0.f, ts2 = 0.f;
        #pragma unroll
        for (int i = 0; i < 8; i++) { ts += shs[i]; ts2 += shs2[i]; }
        float inv_n = 1.f / (float)(NCPG * NHW);
        float mean = ts * inv_n;
        float var  = ts2 * inv_n - mean * mean;
        mm = mean; rr = rsqrtf(var + EPSV);
    }
    __syncthreads();
    if (threadIdx.x < NCPG) {
        int ch = g * NCPG + threadIdx.x;
        float wv = gw[ch], bv = gb[ch];
        g_sc[b * ND + ch] = rr * wv;
        g_sh[b * ND + ch] = bv - mm * rr * wv;
    }
}

// ---------------------------------------------------------------------------
// x [b][c][p] --(GN affine + transpose)--> xn fp16 [b][p][c]
// ---------------------------------------------------------------------------
__global__ void xn_conv_k(const float* __restrict__ x, int bz0)
{
    __shared__ float t[32][33];
    int b = blockIdx.z + bz0, p0 = blockIdx.x * 32, c0 = blockIdx.y * 32;
    int tx = threadIdx.x, ty = threadIdx.y;
    const float* xb = x + (size_t)b * ND * NHW;
    #pragma unroll
    for (int r = 0; r < 4; r++) {
        int c = c0 + ty + 8 * r;
        t[ty + 8 * r][tx] = xb[(size_t)c * NHW + p0 + tx] * g_sc[b * ND + c] + g_sh[b * ND + c];
    }
    __syncthreads();
    int w  = ty * 32 + tx;        // 0..255
    int ci = (w & 15) * 2;
    int pr = w >> 4;              // 0..15
    #pragma unroll
    for (int r2 = 0; r2 < 2; r2++) {
        int pp = pr + 16 * r2;
        __half2 hv = __floats2half2_rn(t[ci][pp], t[ci + 1][pp]);
        *(__half2*)(g_xnh + ((size_t)b * NHW + p0 + pp) * ND + c0 + ci) = hv;
    }
}

// ---------------------------------------------------------------------------
// LayerNorm on context rows -> cn fp16
// ---------------------------------------------------------------------------
__global__ void ln_k(const float* __restrict__ ctx,
                     const float* __restrict__ lw,
                     const float* __restrict__ lb)
{
    int row = blockIdx.x;
    const float* p = ctx + (size_t)row * NCTX;
    float v[3];
    float s = 0.f, s2 = 0.f;
    #pragma unroll
    for (int r = 0; r < 3; r++) {
        v[r] = p[threadIdx.x + r * 256];
        s += v[r]; s2 += v[r] * v[r];
    }
    #pragma unroll
    for (int o = 16; o > 0; o >>= 1) {
        s  += __shfl_down_sync(0xffffffffu, s,  o);
        s2 += __shfl_down_sync(0xffffffffu, s2, o);
    }
    __shared__ float shs[8], shs2[8];
    int lane = threadIdx.x & 31, w = threadIdx.x >> 5;
    if (lane == 0) { shs[w] = s; shs2[w] = s2; }
    __syncthreads();
    __shared__ float mm, rr;
    if (threadIdx.x == 0) {
        float ts = 0.f, ts2 = 0.f;
        #pragma unroll
        for (int i = 0; i < 8; i++) { ts += shs[i]; ts2 += shs2[i]; }
        float inv_n = 1.f / (float)NCTX;
        float mean = ts * inv_n;
        float var  = ts2 * inv_n - mean * mean;
        mm = mean; rr = rsqrtf(var + EPSV);
    }
    __syncthreads();
    #pragma unroll
    for (int r = 0; r < 3; r++) {
        int i = threadIdx.x + r * 256;
        float val = (v[r] - mm) * rr * lw[i] + lb[i];
        g_cnh[(size_t)row * NCTX + i] = __float2half_rn(val);
    }
}

// ---------------------------------------------------------------------------
// weights fp32 -> fp16
// ---------------------------------------------------------------------------
__global__ void convw1_k(const float* __restrict__ w, h16* __restrict__ hi, int n)
{
    int i = blockIdx.x * 1024 + threadIdx.x * 4;
    if (i < n) {
        float4 v = *(const float4*)(w + i);
        *(__half2*)(hi + i)     = __floats2half2_rn(v.x, v.y);
        *(__half2*)(hi + i + 2) = __floats2half2_rn(v.z, v.w);
    }
}

// ---------------------------------------------------------------------------
// PTX helpers
// ---------------------------------------------------------------------------
__device__ __forceinline__ uint32_t smem_u32(const void* p) {
    uint32_t a;
    asm("{.reg .u64 t; cvta.to.shared.u64 t, %1; cvt.u32.u64 %0, t;}" : "=r"(a) : "l"(p));
    return a;
}
__device__ __forceinline__ void mma16816(float* d, const uint32_t* a, const uint32_t* b)
{
    asm volatile(
        "mma.sync.aligned.m16n8k16.row.col.f32.f16.f16.f32 "
        "{%0,%1,%2,%3},{%4,%5,%6,%7},{%8,%9},{%0,%1,%2,%3};"
        : "+f"(d[0]), "+f"(d[1]), "+f"(d[2]), "+f"(d[3])
        : "r"(a[0]), "r"(a[1]), "r"(a[2]), "r"(a[3]), "r"(b[0]), "r"(b[1]));
}
__device__ __forceinline__ void ldsm4(uint32_t& r0, uint32_t& r1, uint32_t& r2,
                                      uint32_t& r3, uint32_t addr)
{
    asm volatile("ldmatrix.sync.aligned.m8n8.x4.shared.b16 {%0,%1,%2,%3},[%4];"
        : "=r"(r0), "=r"(r1), "=r"(r2), "=r"(r3) : "r"(addr));
}
__device__ __forceinline__ void cpa16(uint32_t saddr, const void* gaddr)
{
    asm volatile("cp.async.cg.shared.global [%0],[%1],16;" :: "r"(saddr), "l"(gaddr));
}
#define CP_COMMIT() asm volatile("cp.async.commit_group;" ::: "memory")

// ---------------------------------------------------------------------------
// fp16 GEMM: C[M,N] = A(MxK)*B(KxN); A [m][k], B [n][k]. bz = blockIdx.z + bz0.
// Block 128x128, BK=16, 256 threads (8 warps, warp 64x32), 3-stage cp.async.
// EPI 1: fp16 C = acc (+bias[n]); EPI 2: fp16 C = acc + bias[m];
// EPI 3: fp32 C = acc + bias[m] + resid.
// ---------------------------------------------------------------------------
constexpr int PLA  = 128 * 12 * 4;
constexpr int GST  = 2 * PLA;
constexpr int GSM  = 3 * GST;

template<int EPI>
__global__ __launch_bounds__(256, 2)
void gemm_fp16(const h16* __restrict__ Ah, const h16* __restrict__ Bh,
               void* __restrict__ C0,
               const float* __restrict__ bias, const float* __restrict__ resid,
               int K, int lda, int ldb, int ldc,
               long sA, long sB, long sC, int bz0)
{
    extern __shared__ __align__(16) char dsm[];
    const uint32_t sbase = smem_u32(dsm);
    const int tid = threadIdx.x, lane = tid & 31, wid = tid >> 5;
    const int bz = blockIdx.z + bz0;
    const int m0 = blockIdx.x * 128;
    const int n0 = blockIdx.y * 128;

    const h16* Ap = Ah + (size_t)bz * sA;
    const h16* Bp = Bh + (size_t)bz * sB;
    const int nIter = K >> 4;

    const int lrow = tid >> 1, lch = tid & 1;
    const uint32_t so = (uint32_t)((lrow * 12 + lch * 4) * 4);
    const size_t gAo = (size_t)(m0 + lrow) * lda + lch * 8;
    const size_t gBo = (size_t)(n0 + lrow) * ldb + lch * 8;

    auto issue = [&](int s) {
        int k0 = s << 4;
        uint32_t st = sbase + (s % 3) * GST;
        cpa16(st + so,       Ap + gAo + k0);
        cpa16(st + PLA + so, Bp + gBo + k0);
        CP_COMMIT();
    };

    const int mw = (wid & 1) * 64, nw = (wid >> 1) * 32;
    const int lr = lane & 7;
    const uint32_t aoff = (uint32_t)(((mw + lr + 8 * ((lane >> 3) & 1)) * 12
                                      + (lane >> 4) * 4) * 4);
    const uint32_t boff = (uint32_t)(((nw + 8 * (lane >> 4) + lr) * 12
                                      + ((lane >> 3) & 1) * 4) * 4);
    const int g = lane >> 2, tg = lane & 3;

    float acc[4][4][4];
    #pragma unroll
    for (int i = 0; i < 4; i++)
        #pragma unroll
        for (int j = 0; j < 4; j++)
            #pragma unroll
            for (int q = 0; q < 4; q++) acc[i][j][q] = 0.f;

    issue(0); issue(1);

    for (int it = 0; it < nIter; it++) {
        if (it + 1 < nIter) asm volatile("cp.async.wait_group 1;" ::: "memory");
        else                asm volatile("cp.async.wait_group 0;" ::: "memory");
        __syncthreads();
        if (it + 2 < nIter) issue(it + 2);

        uint32_t st = sbase + (it % 3) * GST;
        uint32_t af[4][4], bh[4][2];
        ldsm4(bh[0][0], bh[0][1], bh[1][0], bh[1][1], st + PLA + boff);
        ldsm4(bh[2][0], bh[2][1], bh[3][0], bh[3][1], st + PLA + boff + 768);
        #pragma unroll
        for (int i = 0; i < 4; i++)
            ldsm4(af[i][0], af[i][1], af[i][2], af[i][3], st + aoff + i * 768);
        #pragma unroll
        for (int i = 0; i < 4; i++)
            #pragma unroll
            for (int j = 0; j < 4; j++)
                mma16816(acc[i][j], af[i], bh[j]);
    }

    if constexpr (EPI == 1 || EPI == 2) {
        h16* Ch = (h16*)C0 + (size_t)bz * sC;
        #pragma unroll
        for (int i = 0; i < 4; i++) {
            int r = m0 + mw + 16 * i + g;
            #pragma unroll
            for (int j = 0; j < 4; j++) {
                int c = n0 + nw + 8 * j + 2 * tg;
                float b0, b1, b2, b3;
                if constexpr (EPI == 1) {
                    b0 = bias ? bias[c] : 0.f; b1 = bias ? bias[c + 1] : 0.f;
                    b2 = b0; b3 = b1;
                } else {
                    b0 = b1 = bias[r]; b2 = b3 = bias[r + 8];
                }
                *(__half2*)(Ch + (size_t)r * ldc + c) =
                    __floats2half2_rn(acc[i][j][0] + b0, acc[i][j][1] + b1);
                *(__half2*)(Ch + (size_t)(r + 8) * ldc + c) =
                    __floats2half2_rn(acc[i][j][2] + b2, acc[i][j][3] + b3);
            }
        }
    } else {
        float* Co = (float*)C0 + (size_t)bz * sC;
        const float* R = resid + (size_t)bz * sC;
        #pragma unroll
        for (int i = 0; i < 4; i++) {
            int r = m0 + mw + 16 * i + g;
            float bv0 = bias[r], bv1 = bias[r + 8];
            #pragma unroll
            for (int j = 0; j < 4; j++) {
                int c = n0 + nw + 8 * j + 2 * tg;
                float2 rv0 = *(const float2*)(R + (size_t)r * ldc + c);
                float2 rv1 = *(const float2*)(R + (size_t)(r + 8) * ldc + c);
                *(float2*)(Co + (size_t)r * ldc + c) =
                    make_float2(acc[i][j][0] + bv0 + rv0.x, acc[i][j][1] + bv0 + rv0.y);
                *(float2*)(Co + (size_t)(r + 8) * ldc + c) =
                    make_float2(acc[i][j][2] + bv1 + rv1.x, acc[i][j][3] + bv1 + rv1.y);
            }
        }
    }
}

// ---------------------------------------------------------------------------
// Fused sim -> softmax -> PV.  Tile: 128 queries x S=256 x full out D=512.
// 512 threads (16 warps: 2 m x 8 n). P kept in smem (swizzled 512B rows).
// First V stages prefetched under softmax.
// ---------------------------------------------------------------------------
constexpr int ASPA = 128 * 12 * 4;        // 6144  (q plane)
constexpr int ASPB = 256 * 12 * 4;        // 12288 (k/v plane)
constexpr int ASST = ASPA + ASPB;         // 18432 per stage
constexpr int APOFF = 3 * ASST;           // 55296 (P tile, 64KB)
constexpr int ARM  = APOFF + 65536;       // 120832
constexpr int ARS  = ARM + 4608;          // 125440
constexpr int ASM  = ARS + 4608;          // 130048

__global__ __launch_bounds__(512)
void attn_k(const h16* __restrict__ qh, const h16* __restrict__ kh,
            const h16* __restrict__ vh, float qscale, int b0)
{
    extern __shared__ __align__(16) char dsm[];
    const uint32_t sbase = smem_u32(dsm);
    float* redM = (float*)(dsm + ARM);
    float* redS = (float*)(dsm + ARS);
    const int tid = threadIdx.x, lane = tid & 31, wid = tid >> 5;
    const int b = blockIdx.y + b0, p0 = blockIdx.x * 128;

    const h16* Qp = qh + (size_t)b * NHW * ND;
    const h16* Kp = kh + (size_t)b * NS * ND;
    const h16* Vp = vh + (size_t)b * ND * NS;

    const int lrow = tid >> 1, lch = tid & 1;
    const uint32_t so = (uint32_t)((lrow * 12 + lch * 4) * 4);

    const int mwp = wid & 1, nwp = wid >> 1;
    const int mw = mwp * 64, nw = nwp * 32;
    const int lr = lane & 7;
    const uint32_t aoff = (uint32_t)(((mw + lr + 8 * ((lane >> 3) & 1)) * 12
                                      + (lane >> 4) * 4) * 4);
    const uint32_t boff = (uint32_t)(((nw + 8 * (lane >> 4) + lr) * 12
                                      + ((lane >> 3) & 1) * 4) * 4);
    const int g = lane >> 2, tg = lane & 3;

    float acc[4][4][4];
    #pragma unroll
    for (int i = 0; i < 4; i++)
        #pragma unroll
        for (int j = 0; j < 4; j++)
            #pragma unroll
            for (int q = 0; q < 4; q++) acc[i][j][q] = 0.f;

    // ---------------- phase 1: sim = q @ k^T ----------------
    auto issueQK = [&](int s) {
        int k0 = s << 4;
        uint32_t st = sbase + (s % 3) * ASST;
        if (tid < 256)
            cpa16(st + so, Qp + (size_t)(p0 + lrow) * ND + k0 + lch * 8);
        cpa16(st + ASPA + so, Kp + (size_t)lrow * ND + k0 + lch * 8);
        CP_COMMIT();
    };
    auto issueV = [&](int s, int nc) {
        int s0 = s << 4;
        uint32_t st = sbase + (s % 3) * ASST;
        cpa16(st + so, Vp + (size_t)(nc * 256 + lrow) * NS + s0 + lch * 8);
        CP_COMMIT();
    };

    issueQK(0); issueQK(1);
    const int nI1 = ND >> 4;   // 32
    for (int it = 0; it < nI1; it++) {
        if (it + 1 < nI1) asm volatile("cp.async.wait_group 1;" ::: "memory");
        else              asm volatile("cp.async.wait_group 0;" ::: "memory");
        __syncthreads();
        if (it + 2 < nI1) issueQK(it + 2);

        uint32_t st = sbase + (it % 3) * ASST;
        uint32_t af[4][4], bh[4][2];
        ldsm4(bh[0][0], bh[0][1], bh[1][0], bh[1][1], st + ASPA + boff);
        ldsm4(bh[2][0], bh[2][1], bh[3][0], bh[3][1], st + ASPA + boff + 768);
        #pragma unroll
        for (int i = 0; i < 4; i++)
            ldsm4(af[i][0], af[i][1], af[i][2], af[i][3], st + aoff + i * 768);
        #pragma unroll
        for (int i = 0; i < 4; i++)
            #pragma unroll
            for (int j = 0; j < 4; j++)
                mma16816(acc[i][j], af[i], bh[j]);
    }

    // prefetch first V stages for nc=0; hidden under softmax.
    // last sim iter (it=31) computed on stage 2; stages 0/1 free for all threads
    // (the it=31-top __syncthreads ordered every thread past stage-0/1 reads).
    issueV(0, 0); issueV(1, 0);

    // ---------------- softmax ----------------
    #pragma unroll
    for (int i = 0; i < 4; i++)
        #pragma unroll
        for (int j = 0; j < 4; j++)
            #pragma unroll
            for (int q = 0; q < 4; q++) acc[i][j][q] *= qscale;

    float rmx[4][2];
    #pragma unroll
    for (int i = 0; i < 4; i++)
        #pragma unroll
        for (int h = 0; h < 2; h++) {
            float m = -1e30f;
            #pragma unroll
            for (int j = 0; j < 4; j++)
                m = fmaxf(m, fmaxf(acc[i][j][2 * h], acc[i][j][2 * h + 1]));
            rmx[i][h] = m;
        }
    #pragma unroll
    for (int o = 1; o <= 2; o <<= 1)
        #pragma unroll
        for (int i = 0; i < 4; i++)
            #pragma unroll
            for (int h = 0; h < 2; h++)
                rmx[i][h] = fmaxf(rmx[i][h], __shfl_xor_sync(0xffffffffu, rmx[i][h], o));
    if (tg == 0) {
        #pragma unroll
        for (int i = 0; i < 4; i++)
            #pragma unroll
            for (int h = 0; h < 2; h++)
                redM[(mw + 16 * i + 8 * h + g) * 9 + nwp] = rmx[i][h];
    }
    __syncthreads();
    float rM[4][2];
    #pragma unroll
    for (int i = 0; i < 4; i++)
        #pragma unroll
        for (int h = 0; h < 2; h++) {
            int R = mw + 16 * i + 8 * h + g;
            float m = -1e30f;
            #pragma unroll
            for (int w = 0; w < 8; w++) m = fmaxf(m, redM[R * 9 + w]);
            rM[i][h] = m;
        }

    float rsm[4][2] = {{0.f,0.f},{0.f,0.f},{0.f,0.f},{0.f,0.f}};
    #pragma unroll
    for (int i = 0; i < 4; i++)
        #pragma unroll
        for (int j = 0; j < 4; j++)
            #pragma unroll
            for (int h = 0; h < 2; h++) {
                float e0 = __expf(acc[i][j][2*h]     - rM[i][h]);
                float e1 = __expf(acc[i][j][2*h + 1] - rM[i][h]);
                acc[i][j][2*h]     = e0;
                acc[i][j][2*h + 1] = e1;
                rsm[i][h] += e0 + e1;
            }
    #pragma unroll
    for (int o = 1; o <= 2; o <<= 1)
        #pragma unroll
        for (int i = 0; i < 4; i++)
            #pragma unroll
            for (int h = 0; h < 2; h++)
                rsm[i][h] += __shfl_xor_sync(0xffffffffu, rsm[i][h], o);
    if (tg == 0) {
        #pragma unroll
        for (int i = 0; i < 4; i++)
            #pragma unroll
            for (int h = 0; h < 2; h++)
                redS[(mw + 16 * i + 8 * h + g) * 9 + nwp] = rsm[i][h];
    }
    __syncthreads();

    // write P to smem (swizzled: unit u of row R at ((u ^ (R&7)) * 16))
    #pragma unroll
    for (int i = 0; i < 4; i++)
        #pragma unroll
        for (int h = 0; h < 2; h++) {
            int R = mw + 16 * i + 8 * h + g;
            float sum = 0.f;
            #pragma unroll
            for (int w = 0; w < 8; w++) sum += redS[R * 9 + w];
            float inv = 1.f / sum;
            #pragma unroll
            for (int j = 0; j < 4; j++) {
                int c = nw + 8 * j + 2 * tg;
                int u = c >> 3;
                char* pa = dsm + APOFF + R * 512 + ((u ^ (R & 7)) << 4) + (c & 7) * 2;
                *(__half2*)pa = __floats2half2_rn(acc[i][j][2*h] * inv,
                                                  acc[i][j][2*h + 1] * inv);
            }
        }
    __syncthreads();

    // ---------------- phase 2: PV = P @ v^T ----------------
    const uint32_t Pb = sbase + APOFF;
    const int arow = mw + (lane & 15);
    const uint32_t swz = (uint32_t)(arow & 7);
    const uint32_t uo = (uint32_t)(lane >> 4);
    uint32_t rowA[4];
    #pragma unroll
    for (int i = 0; i < 4; i++) rowA[i] = Pb + (arow + 16 * i) * 512;

    h16* Cp = g_aoh + ((size_t)b * NHW + p0) * ND;

    #pragma unroll 1
    for (int nc = 0; nc < 2; nc++) {
        #pragma unroll
        for (int i = 0; i < 4; i++)
            #pragma unroll
            for (int j = 0; j < 4; j++)
                #pragma unroll
                for (int q = 0; q < 4; q++) acc[i][j][q] = 0.f;

        if (nc == 1) { issueV(0, 1); issueV(1, 1); }  // after nc=0 tail sync

        const int nI2 = NS >> 4;   // 16
        for (int it = 0; it < nI2; it++) {
            if (it + 1 < nI2) asm volatile("cp.async.wait_group 1;" ::: "memory");
            else              asm volatile("cp.async.wait_group 0;" ::: "memory");
            __syncthreads();
            if (it + 2 < nI2) issueV(it + 2, nc);

            uint32_t st = sbase + (it % 3) * ASST;
            uint32_t af[4][4], bh[4][2];
            ldsm4(bh[0][0], bh[0][1], bh[1][0], bh[1][1], st + boff);
            ldsm4(bh[2][0], bh[2][1], bh[3][0], bh[3][1], st + boff + 768);
            #pragma unroll
            for (int i = 0; i < 4; i++) {
                uint32_t ua = ((2u * (uint32_t)it + uo) ^ swz) << 4;
                ldsm4(af[i][0], af[i][1], af[i][2], af[i][3], rowA[i] + ua);
            }
            #pragma unroll
            for (int i = 0; i < 4; i++)
                #pragma unroll
                for (int j = 0; j < 4; j++)
                    mma16816(acc[i][j], af[i], bh[j]);
        }

        // epilogue: write ao chunk
        #pragma unroll
        for (int i = 0; i < 4; i++) {
            int r = mw + 16 * i + g;
            #pragma unroll
            for (int j = 0; j < 4; j++) {
                int c = nc * 256 + nw + 8 * j + 2 * tg;
                *(__half2*)(Cp + (size_t)r * ND + c) =
                    __floats2half2_rn(acc[i][j][0], acc[i][j][1]);
                *(__half2*)(Cp + (size_t)(r + 8) * ND + c) =
                    __floats2half2_rn(acc[i][j][2], acc[i][j][3]);
            }
        }
        __syncthreads();
    }
}

// ---------------------------------------------------------------------------
extern "C" void kernel_launch(void* const* d_in, const int* in_sizes, int n_in,
                              void* d_out, int out_size)
{
    const float* x    = (const float*)d_in[0];
    const float* ctx  = (const float*)d_in[1];
    const float* gn_w = (const float*)d_in[2];
    const float* gn_b = (const float*)d_in[3];
    const float* ln_w = (const float*)d_in[4];
    const float* ln_b = (const float*)d_in[5];
    const float* wq   = (const float*)d_in[6];
    const float* bq   = (const float*)d_in[7];
    const float* wkv  = (const float*)d_in[8];
    const float* bkv  = (const float*)d_in[9];
    const float* wo   = (const float*)d_in[10];
    const float* bo   = (const float*)d_in[11];
    float* out = (float*)d_out;

    cudaFuncSetAttribute(gemm_fp16<1>, cudaFuncAttributeMaxDynamicSharedMemorySize, GSM);
    cudaFuncSetAttribute(gemm_fp16<2>, cudaFuncAttributeMaxDynamicSharedMemorySize, GSM);
    cudaFuncSetAttribute(gemm_fp16<3>, cudaFuncAttributeMaxDynamicSharedMemorySize, GSM);
    cudaFuncSetAttribute(attn_k, cudaFuncAttributeMaxDynamicSharedMemorySize, ASM);

    h16 *xnh, *qh, *aoh, *cnh, *kh, *vh, *wqh, *wkvh, *woh;
    cudaGetSymbolAddress((void**)&xnh, g_xnh);
    cudaGetSymbolAddress((void**)&qh,  g_qh);
    cudaGetSymbolAddress((void**)&aoh, g_aoh);
    cudaGetSymbolAddress((void**)&cnh, g_cnh);
    cudaGetSymbolAddress((void**)&kh,  g_kh);
    cudaGetSymbolAddress((void**)&vh,  g_vh);
    cudaGetSymbolAddress((void**)&wqh, g_wqh);
    cudaGetSymbolAddress((void**)&wkvh, g_wkvh);
    cudaGetSymbolAddress((void**)&woh, g_woh);

    const float qscale = 0.044194173824159216f; // 512^-0.5
    const int HB = NB / 2;  // half batch

    static cudaStream_t s1 = nullptr, s2 = nullptr, s3 = nullptr;
    static cudaEvent_t eF = nullptr, eWq = nullptr, eV = nullptr, eWo = nullptr,
                       eWkv = nullptr, eB = nullptr;
    static bool sinit = false, ms = false;
    if (!sinit) {
        sinit = true;
        ms = (cudaStreamCreateWithFlags(&s1, cudaStreamNonBlocking) == cudaSuccess)
          && (cudaStreamCreateWithFlags(&s2, cudaStreamNonBlocking) == cudaSuccess)
          && (cudaStreamCreateWithFlags(&s3, cudaStreamNonBlocking) == cudaSuccess)
          && (cudaEventCreateWithFlags(&eF,   cudaEventDisableTiming) == cudaSuccess)
          && (cudaEventCreateWithFlags(&eWq,  cudaEventDisableTiming) == cudaSuccess)
          && (cudaEventCreateWithFlags(&eV,   cudaEventDisableTiming) == cudaSuccess)
          && (cudaEventCreateWithFlags(&eWo,  cudaEventDisableTiming) == cudaSuccess)
          && (cudaEventCreateWithFlags(&eWkv, cudaEventDisableTiming) == cudaSuccess)
          && (cudaEventCreateWithFlags(&eB,   cudaEventDisableTiming) == cudaSuccess);
    }

    if (ms) {
        cudaEventRecord(eF, 0);
        cudaStreamWaitEvent(s1, eF, 0);
        cudaStreamWaitEvent(s2, eF, 0);
        cudaStreamWaitEvent(s3, eF, 0);

        // s3: weight conversions
        convw1_k<<<(ND * ND + 1023) / 1024, 256, 0, s3>>>(wq, wqh, ND * ND);
        cudaEventRecord(eWq, s3);
        convw1_k<<<(1024 * NCTX + 1023) / 1024, 256, 0, s3>>>(wkv, wkvh, 1024 * NCTX);
        cudaEventRecord(eWkv, s3);
        convw1_k<<<(ND * ND + 1023) / 1024, 256, 0, s3>>>(wo, woh, ND * ND);
        cudaEventRecord(eWo, s3);

        // s2: context path (all 16 batches)
        ln_k<<<NB * NS, 256, 0, s2>>>(ctx, ln_w, ln_b);
        cudaStreamWaitEvent(s2, eWkv, 0);
        gemm_fp16<1><<<dim3(NS / 128, ND / 128, NB), 256, GSM, s2>>>(
            cnh, wkvh, kh, bkv, nullptr, NCTX, NCTX, NCTX, ND,
            (long)NS * NCTX, 0L, (long)NS * ND, 0);
        gemm_fp16<2><<<dim3(ND / 128, NS / 128, NB), 256, GSM, s2>>>(
            wkvh + (size_t)512 * NCTX, cnh, vh, bkv + 512, nullptr,
            NCTX, NCTX, NCTX, NS, 0L, (long)NS * NCTX, (long)ND * NS, 0);
        cudaEventRecord(eV, s2);

        // x-path half A on stream 0, half B on s1
        gn_stats_k<<<HB * 32, 256>>>(x, gn_w, gn_b, 0);
        gn_stats_k<<<HB * 32, 256, 0, s1>>>(x, gn_w, gn_b, HB * 32);
        xn_conv_k<<<dim3(NHW / 32, ND / 32, HB), dim3(32, 8)>>>(x, 0);
        xn_conv_k<<<dim3(NHW / 32, ND / 32, HB), dim3(32, 8), 0, s1>>>(x, HB);

        cudaStreamWaitEvent(0,  eWq, 0);
        cudaStreamWaitEvent(s1, eWq, 0);
        gemm_fp16<1><<<dim3(NHW / 128, ND / 128, HB), 256, GSM>>>(
            xnh, wqh, qh, bq, nullptr, ND, ND, ND, ND,
            (long)NHW * ND, 0L, (long)NHW * ND, 0);
        gemm_fp16<1><<<dim3(NHW / 128, ND / 128, HB), 256, GSM, s1>>>(
            xnh, wqh, qh, bq, nullptr, ND, ND, ND, ND,
            (long)NHW * ND, 0L, (long)NHW * ND, HB);

        cudaStreamWaitEvent(0,  eV, 0);
        cudaStreamWaitEvent(s1, eV, 0);
        attn_k<<<dim3(NHW / 128, HB), 512, ASM>>>(qh, kh, vh, qscale, 0);
        attn_k<<<dim3(NHW / 128, HB), 512, ASM, s1>>>(qh, kh, vh, qscale, HB);

        cudaStreamWaitEvent(0,  eWo, 0);
        cudaStreamWaitEvent(s1, eWo, 0);
        gemm_fp16<3><<<dim3(ND / 128, NHW / 128, HB), 256, GSM>>>(
            woh, aoh, out, bo, x, ND, ND, ND, NHW,
            0L, (long)NHW * ND, (long)ND * NHW, 0);
        gemm_fp16<3><<<dim3(ND / 128, NHW / 128, HB), 256, GSM, s1>>>(
            woh, aoh, out, bo, x, ND, ND, ND, NHW,
            0L, (long)NHW * ND, (long)ND * NHW, HB);
        cudaEventRecord(eB, s1);
        cudaStreamWaitEvent(0, eB, 0);   // join s1 back into capture origin
    } else {
        // serial fallback
        convw1_k<<<(ND * ND + 1023) / 1024, 256>>>(wq, wqh, ND * ND);
        convw1_k<<<(1024 * NCTX + 1023) / 1024, 256>>>(wkv, wkvh, 1024 * NCTX);
        convw1_k<<<(ND * ND + 1023) / 1024, 256>>>(wo, woh, ND * ND);
        gn_stats_k<<<NB * 32, 256>>>(x, gn_w, gn_b, 0);
        ln_k<<<NB * NS, 256>>>(ctx, ln_w, ln_b);
        xn_conv_k<<<dim3(NHW / 32, ND / 32, NB), dim3(32, 8)>>>(x, 0);
        gemm_fp16<1><<<dim3(NS / 128, ND / 128, NB), 256, GSM>>>(
            cnh, wkvh, kh, bkv, nullptr, NCTX, NCTX, NCTX, ND,
            (long)NS * NCTX, 0L, (long)NS * ND, 0);
        gemm_fp16<2><<<dim3(ND / 128, NS / 128, NB), 256, GSM>>>(
            wkvh + (size_t)512 * NCTX, cnh, vh, bkv + 512, nullptr,
            NCTX, NCTX, NCTX, NS, 0L, (long)NS * NCTX, (long)ND * NS, 0);
        gemm_fp16<1><<<dim3(NHW / 128, ND / 128, NB), 256, GSM>>>(
            xnh, wqh, qh, bq, nullptr, ND, ND, ND, ND,
            (long)NHW * ND, 0L, (long)NHW * ND, 0);
        attn_k<<<dim3(NHW / 128, NB), 512, ASM>>>(qh, kh, vh, qscale, 0);
        gemm_fp16<3><<<dim3(ND / 128, NHW / 128, NB), 256, GSM>>>(
            woh, aoh, out, bo, x, ND, ND, ND, NHW,
            0L, (long)NHW * ND, (long)ND * NHW, 0);
    }
}